// round 1
// baseline (speedup 1.0000x reference)
#include <cuda_runtime.h>

#define TPB 256
#define NGPB 16   // groups (of 32 inputs) per block in the main kernel

// Coefficient build tables: 34 (mask-piece, x-offset, scale) entries per 32-input group.
// Piece value as u32 == q * 2^s exactly; coefficient = x[off] * 2^-s so fma gives q*x exactly.
__device__ const int KOFF[34] = {
    0,1,2,3,4,5,6,7,8,9,      // r0 fields j=0..9 (bits 3j..3j+2)
    10,10,                    // w10 pieces: (r0>>30)&3, (r1&1)<<2
    11,12,13,14,15,16,17,18,19,20,  // r1 fields j=0..9 (bits 3j+1..)
    21,21,                    // w21 pieces: (r1>>31)&1, (r2&3)<<1
    22,23,24,25,26,27,28,29,30,31   // r2 fields j=0..9 (bits 3j+2..)
};
__device__ const float KSCALE[34] = {
    0x1p0f, 0x1p-3f, 0x1p-6f, 0x1p-9f, 0x1p-12f, 0x1p-15f, 0x1p-18f, 0x1p-21f, 0x1p-24f, 0x1p-27f,
    0x1p-30f, 4.0f,
    0x1p-1f, 0x1p-4f, 0x1p-7f, 0x1p-10f, 0x1p-13f, 0x1p-16f, 0x1p-19f, 0x1p-22f, 0x1p-25f, 0x1p-28f,
    0x1p-31f, 2.0f,
    0x1p-2f, 0x1p-5f, 0x1p-8f, 0x1p-11f, 0x1p-14f, 0x1p-17f, 0x1p-20f, 0x1p-23f, 0x1p-26f, 0x1p-29f
};

__device__ __forceinline__ float uf(unsigned v) { return __uint2float_rn(v); }

// Kernel 1: out[o] = bias[o] - zeros[o]*sum(x) + sum_j oweight[o,j]*x[outlieridx[j]]
__global__ __launch_bounds__(TPB)
void k_const(const float* __restrict__ x,
             const float* __restrict__ zeros,
             const float* __restrict__ bias,
             const float* __restrict__ oweight,
             const int*   __restrict__ outlieridx,
             float* __restrict__ out,
             int INF, int NOUT)
{
    __shared__ float red[TPB];
    __shared__ float xo[256];
    const int tid = threadIdx.x;

    float s = 0.f;
    for (int i = tid; i < INF; i += TPB) s += x[i];
    red[tid] = s;
    __syncthreads();
    for (int o = TPB / 2; o > 0; o >>= 1) {
        if (tid < o) red[tid] += red[tid + o];
        __syncthreads();
    }
    if (tid < NOUT) xo[tid] = x[outlieridx[tid]];
    __syncthreads();

    const float sumx = red[0];
    const int o = blockIdx.x * TPB + tid;
    float acc = bias[o] - zeros[o] * sumx;
    const float4* ow4 = (const float4*)(oweight + (size_t)o * NOUT);
    #pragma unroll 4
    for (int j = 0; j < NOUT / 4; ++j) {
        float4 w = ow4[j];
        acc = fmaf(w.x, xo[4 * j + 0], acc);
        acc = fmaf(w.y, xo[4 * j + 1], acc);
        acc = fmaf(w.z, xo[4 * j + 2], acc);
        acc = fmaf(w.w, xo[4 * j + 3], acc);
    }
    out[o] = acc;
}

// Kernel 2: out[o] += scales[o] * sum_k x[k]*q[k,o] over this block's K-chunk.
__global__ __launch_bounds__(TPB)
void k_main(const float* __restrict__ x,
            const int*   __restrict__ qw,
            const float* __restrict__ scales,
            float* __restrict__ out,
            int OUTF)
{
    __shared__ __align__(16) float cs[NGPB * 36];

    const int tid = threadIdx.x;
    const int gbase = blockIdx.y * NGPB;

    // Build prescaled coefficient table for this K-chunk (shared across all 256 outputs).
    for (int idx = tid; idx < NGPB * 34; idx += TPB) {
        int g = idx / 34, k = idx - g * 34;
        cs[g * 36 + k] = x[(gbase + g) * 32 + KOFF[k]] * KSCALE[k];
    }
    __syncthreads();

    const int o = blockIdx.x * TPB + tid;
    const int* col = qw + o;
    const long rbase = (long)gbase * 3;

    float a0 = 0.f, a1 = 0.f, a2 = 0.f, a3 = 0.f;

    #pragma unroll 2
    for (int g = 0; g < NGPB; ++g) {
        unsigned r0 = (unsigned)col[(rbase + 3 * g + 0) * OUTF];
        unsigned r1 = (unsigned)col[(rbase + 3 * g + 1) * OUTF];
        unsigned r2 = (unsigned)col[(rbase + 3 * g + 2) * OUTF];

        const float4* cp = (const float4*)&cs[g * 36];
        float4 q0 = cp[0], q1 = cp[1], q2 = cp[2], q3 = cp[3], q4 = cp[4];
        float4 q5 = cp[5], q6 = cp[6], q7 = cp[7], q8 = cp[8];

        a0 = fmaf(uf(r0 & 0x00000007u), q0.x, a0);
        a1 = fmaf(uf(r0 & 0x00000038u), q0.y, a1);
        a2 = fmaf(uf(r0 & 0x000001C0u), q0.z, a2);
        a3 = fmaf(uf(r0 & 0x00000E00u), q0.w, a3);
        a0 = fmaf(uf(r0 & 0x00007000u), q1.x, a0);
        a1 = fmaf(uf(r0 & 0x00038000u), q1.y, a1);
        a2 = fmaf(uf(r0 & 0x001C0000u), q1.z, a2);
        a3 = fmaf(uf(r0 & 0x00E00000u), q1.w, a3);
        a0 = fmaf(uf(r0 & 0x07000000u), q2.x, a0);
        a1 = fmaf(uf(r0 & 0x38000000u), q2.y, a1);
        a2 = fmaf(uf(r0 & 0xC0000000u), q2.z, a2);   // w10 lo piece
        a3 = fmaf(uf(r1 & 0x00000001u), q2.w, a3);   // w10 hi piece (*4)
        a0 = fmaf(uf(r1 & 0x0000000Eu), q3.x, a0);
        a1 = fmaf(uf(r1 & 0x00000070u), q3.y, a1);
        a2 = fmaf(uf(r1 & 0x00000380u), q3.z, a2);
        a3 = fmaf(uf(r1 & 0x00001C00u), q3.w, a3);
        a0 = fmaf(uf(r1 & 0x0000E000u), q4.x, a0);
        a1 = fmaf(uf(r1 & 0x00070000u), q4.y, a1);
        a2 = fmaf(uf(r1 & 0x00380000u), q4.z, a2);
        a3 = fmaf(uf(r1 & 0x01C00000u), q4.w, a3);
        a0 = fmaf(uf(r1 & 0x0E000000u), q5.x, a0);
        a1 = fmaf(uf(r1 & 0x70000000u), q5.y, a1);
        a2 = fmaf(uf(r1 & 0x80000000u), q5.z, a2);   // w21 lo piece
        a3 = fmaf(uf(r2 & 0x00000003u), q5.w, a3);   // w21 hi piece (*2)
        a0 = fmaf(uf(r2 & 0x0000001Cu), q6.x, a0);
        a1 = fmaf(uf(r2 & 0x000000E0u), q6.y, a1);
        a2 = fmaf(uf(r2 & 0x00000700u), q6.z, a2);
        a3 = fmaf(uf(r2 & 0x00003800u), q6.w, a3);
        a0 = fmaf(uf(r2 & 0x0001C000u), q7.x, a0);
        a1 = fmaf(uf(r2 & 0x000E0000u), q7.y, a1);
        a2 = fmaf(uf(r2 & 0x00700000u), q7.z, a2);
        a3 = fmaf(uf(r2 & 0x03800000u), q7.w, a3);
        a0 = fmaf(uf(r2 & 0x1C000000u), q8.x, a0);
        a1 = fmaf(uf(r2 & 0xE0000000u), q8.y, a1);
    }

    const float acc = (a0 + a1) + (a2 + a3);
    atomicAdd(&out[o], scales[o] * acc);
}

extern "C" void kernel_launch(void* const* d_in, const int* in_sizes, int n_in,
                              void* d_out, int out_size)
{
    const float* x      = (const float*)d_in[0];
    const int*   qw     = (const int*)  d_in[1];
    const float* scales = (const float*)d_in[2];
    const float* zeros  = (const float*)d_in[3];
    const float* bias   = (const float*)d_in[4];
    const float* ow     = (const float*)d_in[5];
    const int*   oidx   = (const int*)  d_in[6];
    float* out = (float*)d_out;

    const int INF  = in_sizes[0];          // 8192
    const int OUTF = in_sizes[2];          // 8192
    const int NOUT = in_sizes[6];          // 64
    const int ngroups = INF / 32;          // 256

    k_const<<<OUTF / TPB, TPB>>>(x, zeros, bias, ow, oidx, out, INF, NOUT);

    dim3 grid(OUTF / TPB, ngroups / NGPB); // (32, 16) = 512 blocks
    k_main<<<grid, TPB>>>(x, qw, scales, out, OUTF);
}

// round 2
// speedup vs baseline: 1.0965x; 1.0965x over previous
#include <cuda_runtime.h>

#define KTPB 256      // k_const block size
#define TPB  128      // k_main block size
#define NGPB 4        // groups (of 32 inputs) per block in k_main
#define CPT  4        // output columns per thread

typedef unsigned long long ull;

// Coefficient table: 34 entries per group, in PAIR order (entries 2p, 2p+1 form f32x2 pair p).
// Field value as float (after magic-subtract) == q * 2^s exactly; coeff = x[off] * KSCALE
// so fma gives q*x exactly.
__device__ const int KOFF[34] = {
    0,1, 2,3, 4,5, 6,7, 8,9, 10,10, 11,12, 13,14, 15,16, 17,18,
    19,20, 21,21, 22,23, 24,25, 26,27, 28,29, 30,31
};
__device__ const float KSCALE[34] = {
    0x1p0f, 0x1p-3f, 0x1p-6f, 0x1p-9f, 0x1p-12f, 0x1p-15f, 0x1p-18f,   // A fields j=0..6
    0x1p0f, 0x1p-3f, 0x1p-6f,                                          // B fields j=7..9 (r0>>21)
    0x1p-9f,                                                           // w10 lo (B bits 9-10)
    4.0f,                                                              // w10 hi (r1 bit 0)
    0x1p-1f, 0x1p-4f, 0x1p-7f, 0x1p-10f, 0x1p-13f, 0x1p-16f, 0x1p-19f, // C fields j=0..6
    0x1p0f, 0x1p-3f, 0x1p-6f,                                          // D fields j=7..9 (r1>>22)
    0x1p-9f,                                                           // w21 lo (D bit 9)
    2.0f,                                                              // w21 hi (r2 bits 0-1)
    0x1p-2f, 0x1p-5f, 0x1p-8f, 0x1p-11f, 0x1p-14f, 0x1p-17f, 0x1p-20f, // E fields j=0..6
    0x1p0f, 0x1p-3f, 0x1p-6f                                           // F fields j=7..9 (r2>>23)
};

// Kernel 1: out[o] = bias[o] - zeros[o]*sum(x) + sum_j oweight[o,j]*x[outlieridx[j]]
__global__ __launch_bounds__(KTPB)
void k_const(const float* __restrict__ x,
             const float* __restrict__ zeros,
             const float* __restrict__ bias,
             const float* __restrict__ oweight,
             const int*   __restrict__ outlieridx,
             float* __restrict__ out,
             int INF, int NOUT)
{
    __shared__ float red[KTPB];
    __shared__ float xo[256];
    const int tid = threadIdx.x;

    float s = 0.f;
    for (int i = tid; i < INF; i += KTPB) s += x[i];
    red[tid] = s;
    __syncthreads();
    for (int o = KTPB / 2; o > 0; o >>= 1) {
        if (tid < o) red[tid] += red[tid + o];
        __syncthreads();
    }
    if (tid < NOUT) xo[tid] = x[outlieridx[tid]];
    __syncthreads();

    const float sumx = red[0];
    const int o = blockIdx.x * KTPB + tid;
    float acc = bias[o] - zeros[o] * sumx;
    const float4* ow4 = (const float4*)(oweight + (size_t)o * NOUT);
    #pragma unroll 4
    for (int j = 0; j < NOUT / 4; ++j) {
        float4 w = ow4[j];
        acc = fmaf(w.x, xo[4 * j + 0], acc);
        acc = fmaf(w.y, xo[4 * j + 1], acc);
        acc = fmaf(w.z, xo[4 * j + 2], acc);
        acc = fmaf(w.w, xo[4 * j + 3], acc);
    }
    out[o] = acc;
}

// One packed step: two masked fields -> float pair via magic constant, subtract 2^23,
// fma into packed accumulator. 2 LOP3 (alu) + pack + add.f32x2 + fma.f32x2 (fma pipe).
#define PAIR(acc, va, ma, vb, mb, cp) do {                                        \
    ull _t;                                                                       \
    asm("mov.b64 %0, {%1,%2};" : "=l"(_t)                                         \
        : "r"(((va) & (ma)) | 0x4B000000u), "r"(((vb) & (mb)) | 0x4B000000u));    \
    asm("add.rn.f32x2 %0, %0, %1;" : "+l"(_t) : "l"(NEG64));                      \
    asm("fma.rn.f32x2 %0, %1, %2, %0;" : "+l"(acc) : "l"(_t), "l"(cp));           \
} while (0)

__device__ __forceinline__ void docol(ull& a0, ull& a1,
                                      unsigned A, unsigned C, unsigned E,
                                      const ull* __restrict__ cp, ull NEG64)
{
    unsigned B = A >> 21, D = C >> 22, F = E >> 23;
    PAIR(a0, A, 0x00000007u, A, 0x00000038u, cp[0]);
    PAIR(a1, A, 0x000001C0u, A, 0x00000E00u, cp[1]);
    PAIR(a0, A, 0x00007000u, A, 0x00038000u, cp[2]);
    PAIR(a1, A, 0x001C0000u, B, 0x00000007u, cp[3]);
    PAIR(a0, B, 0x00000038u, B, 0x000001C0u, cp[4]);
    PAIR(a1, B, 0x00000600u, C, 0x00000001u, cp[5]);
    PAIR(a0, C, 0x0000000Eu, C, 0x00000070u, cp[6]);
    PAIR(a1, C, 0x00000380u, C, 0x00001C00u, cp[7]);
    PAIR(a0, C, 0x0000E000u, C, 0x00070000u, cp[8]);
    PAIR(a1, C, 0x00380000u, D, 0x00000007u, cp[9]);
    PAIR(a0, D, 0x00000038u, D, 0x000001C0u, cp[10]);
    PAIR(a1, D, 0x00000200u, E, 0x00000003u, cp[11]);
    PAIR(a0, E, 0x0000001Cu, E, 0x000000E0u, cp[12]);
    PAIR(a1, E, 0x00000700u, E, 0x00003800u, cp[13]);
    PAIR(a0, E, 0x0001C000u, E, 0x000E0000u, cp[14]);
    PAIR(a1, E, 0x00700000u, F, 0x00000007u, cp[15]);
    PAIR(a0, F, 0x00000038u, F, 0x000001C0u, cp[16]);
}

// Kernel 2: out[o] += scales[o] * sum_k x[k]*q[k,o] over this block's K-chunk.
// Each thread handles 4 consecutive output columns (int4 loads of qweight).
__global__ __launch_bounds__(TPB)
void k_main(const float* __restrict__ x,
            const int*   __restrict__ qw,
            const float* __restrict__ scales,
            float* __restrict__ out,
            int OUTF)
{
    __shared__ __align__(16) float cs[NGPB * 36];

    const int tid = threadIdx.x;
    const int gbase = blockIdx.y * NGPB;
    const int colbase = blockIdx.x * (TPB * CPT) + tid * CPT;

    // Build prescaled coefficient table for this K-chunk (shared across all columns).
    for (int idx = tid; idx < NGPB * 34; idx += TPB) {
        int g = idx / 34, k = idx - g * 34;
        cs[g * 36 + k] = x[(gbase + g) * 32 + KOFF[k]] * KSCALE[k];
    }
    __syncthreads();

    const ull NEG64 = 0xCB000000CB000000ull;  // packed {-2^23, -2^23}

    ull acc[CPT][2];
    #pragma unroll
    for (int c = 0; c < CPT; ++c) { acc[c][0] = 0ull; acc[c][1] = 0ull; }

    const int rowstride4 = OUTF / 4;  // int4 stride between rows

    #pragma unroll 2
    for (int g = 0; g < NGPB; ++g) {
        const int4* row = (const int4*)(qw + (long)((gbase + g) * 3) * OUTF + colbase);
        int4 w0 = row[0];
        int4 w1 = row[rowstride4];
        int4 w2 = row[2 * rowstride4];

        const ull* cp = (const ull*)&cs[g * 36];

        const unsigned* a = (const unsigned*)&w0;
        const unsigned* c_ = (const unsigned*)&w1;
        const unsigned* e = (const unsigned*)&w2;
        docol(acc[0][0], acc[0][1], a[0], c_[0], e[0], cp, NEG64);
        docol(acc[1][0], acc[1][1], a[1], c_[1], e[1], cp, NEG64);
        docol(acc[2][0], acc[2][1], a[2], c_[2], e[2], cp, NEG64);
        docol(acc[3][0], acc[3][1], a[3], c_[3], e[3], cp, NEG64);
    }

    #pragma unroll
    for (int c = 0; c < CPT; ++c) {
        float s0 = __uint_as_float((unsigned)(acc[c][0]));
        float s1 = __uint_as_float((unsigned)(acc[c][0] >> 32));
        float s2 = __uint_as_float((unsigned)(acc[c][1]));
        float s3 = __uint_as_float((unsigned)(acc[c][1] >> 32));
        float sum = (s0 + s1) + (s2 + s3);
        int o = colbase + c;
        atomicAdd(&out[o], scales[o] * sum);
    }
}

extern "C" void kernel_launch(void* const* d_in, const int* in_sizes, int n_in,
                              void* d_out, int out_size)
{
    const float* x      = (const float*)d_in[0];
    const int*   qw     = (const int*)  d_in[1];
    const float* scales = (const float*)d_in[2];
    const float* zeros  = (const float*)d_in[3];
    const float* bias   = (const float*)d_in[4];
    const float* ow     = (const float*)d_in[5];
    const int*   oidx   = (const int*)  d_in[6];
    float* out = (float*)d_out;

    const int INF  = in_sizes[0];          // 8192
    const int OUTF = in_sizes[2];          // 8192
    const int NOUT = in_sizes[6];          // 64
    const int ngroups = INF / 32;          // 256

    k_const<<<OUTF / KTPB, KTPB>>>(x, zeros, bias, ow, oidx, out, INF, NOUT);

    dim3 grid(OUTF / (TPB * CPT), ngroups / NGPB);  // (16, 64) = 1024 blocks
    k_main<<<grid, TPB>>>(x, qw, scales, out, OUTF);
}

// round 3
// speedup vs baseline: 1.2322x; 1.1237x over previous
#include <cuda_runtime.h>

#define KTPB 128      // k_const block size
#define TPB  128      // k_main block size
#define NGPB 4        // groups (of 32 inputs) per block in k_main
#define CPT  2        // output columns per thread

typedef unsigned long long ull;

// Coefficient table: 34 entries per group, in PAIR order (entries 2p, 2p+1 form f32x2 pair p).
// Field value as float (after magic-subtract) == q * 2^s exactly; coeff = x[off] * KSCALE
// so fma gives q*x exactly.
__device__ const int KOFF[34] = {
    0,1, 2,3, 4,5, 6,7, 8,9, 10,10, 11,12, 13,14, 15,16, 17,18,
    19,20, 21,21, 22,23, 24,25, 26,27, 28,29, 30,31
};
__device__ const float KSCALE[34] = {
    0x1p0f, 0x1p-3f, 0x1p-6f, 0x1p-9f, 0x1p-12f, 0x1p-15f, 0x1p-18f,   // A fields j=0..6
    0x1p0f, 0x1p-3f, 0x1p-6f,                                          // B fields j=7..9 (r0>>21)
    0x1p-9f,                                                           // w10 lo (B bits 9-10)
    4.0f,                                                              // w10 hi (r1 bit 0)
    0x1p-1f, 0x1p-4f, 0x1p-7f, 0x1p-10f, 0x1p-13f, 0x1p-16f, 0x1p-19f, // C fields j=0..6
    0x1p0f, 0x1p-3f, 0x1p-6f,                                          // D fields j=7..9 (r1>>22)
    0x1p-9f,                                                           // w21 lo (D bit 9)
    2.0f,                                                              // w21 hi (r2 bits 0-1)
    0x1p-2f, 0x1p-5f, 0x1p-8f, 0x1p-11f, 0x1p-14f, 0x1p-17f, 0x1p-20f, // E fields j=0..6
    0x1p0f, 0x1p-3f, 0x1p-6f                                           // F fields j=7..9 (r2>>23)
};

// Kernel 1: out[o] = bias[o] - zeros[o]*sum(x) + sum_j oweight[o,j]*x[outlieridx[j]]
__global__ __launch_bounds__(KTPB)
void k_const(const float* __restrict__ x,
             const float* __restrict__ zeros,
             const float* __restrict__ bias,
             const float* __restrict__ oweight,
             const int*   __restrict__ outlieridx,
             float* __restrict__ out,
             int INF, int NOUT)
{
    __shared__ float wred[KTPB / 32];
    __shared__ float xo[64];
    const int tid = threadIdx.x;

    float s = 0.f;
    for (int i = tid; i < INF; i += KTPB) s += x[i];
    #pragma unroll
    for (int d = 16; d > 0; d >>= 1) s += __shfl_xor_sync(0xFFFFFFFFu, s, d);
    if ((tid & 31) == 0) wred[tid >> 5] = s;
    if (tid < NOUT) xo[tid] = x[outlieridx[tid]];
    __syncthreads();

    float sumx = 0.f;
    #pragma unroll
    for (int w = 0; w < KTPB / 32; ++w) sumx += wred[w];

    const int o = blockIdx.x * KTPB + tid;
    float acc = bias[o] - zeros[o] * sumx;
    const float4* ow4 = (const float4*)(oweight + (size_t)o * NOUT);
    #pragma unroll
    for (int j = 0; j < 16; ++j) {
        float4 w = ow4[j];
        acc = fmaf(w.x, xo[4 * j + 0], acc);
        acc = fmaf(w.y, xo[4 * j + 1], acc);
        acc = fmaf(w.z, xo[4 * j + 2], acc);
        acc = fmaf(w.w, xo[4 * j + 3], acc);
    }
    out[o] = acc;
}

// One packed step: two masked fields -> float pair via magic constant, subtract 2^23,
// fma into packed accumulator.
#define PAIR(acc, va, ma, vb, mb, cp) do {                                        \
    ull _t;                                                                       \
    asm("mov.b64 %0, {%1,%2};" : "=l"(_t)                                         \
        : "r"(((va) & (ma)) | 0x4B000000u), "r"(((vb) & (mb)) | 0x4B000000u));    \
    asm("add.rn.f32x2 %0, %0, %1;" : "+l"(_t) : "l"(NEG64));                      \
    asm("fma.rn.f32x2 %0, %1, %2, %0;" : "+l"(acc) : "l"(_t), "l"(cp));           \
} while (0)

__device__ __forceinline__ void docol(ull& a0, ull& a1,
                                      unsigned A, unsigned C, unsigned E,
                                      const ull (&c)[17], ull NEG64)
{
    unsigned B = A >> 21, D = C >> 22, F = E >> 23;
    PAIR(a0, A, 0x00000007u, A, 0x00000038u, c[0]);
    PAIR(a1, A, 0x000001C0u, A, 0x00000E00u, c[1]);
    PAIR(a0, A, 0x00007000u, A, 0x00038000u, c[2]);
    PAIR(a1, A, 0x001C0000u, B, 0x00000007u, c[3]);
    PAIR(a0, B, 0x00000038u, B, 0x000001C0u, c[4]);
    PAIR(a1, B, 0x00000600u, C, 0x00000001u, c[5]);
    PAIR(a0, C, 0x0000000Eu, C, 0x00000070u, c[6]);
    PAIR(a1, C, 0x00000380u, C, 0x00001C00u, c[7]);
    PAIR(a0, C, 0x0000E000u, C, 0x00070000u, c[8]);
    PAIR(a1, C, 0x00380000u, D, 0x00000007u, c[9]);
    PAIR(a0, D, 0x00000038u, D, 0x000001C0u, c[10]);
    PAIR(a1, D, 0x00000200u, E, 0x00000003u, c[11]);
    PAIR(a0, E, 0x0000001Cu, E, 0x000000E0u, c[12]);
    PAIR(a1, E, 0x00000700u, E, 0x00003800u, c[13]);
    PAIR(a0, E, 0x0001C000u, E, 0x000E0000u, c[14]);
    PAIR(a1, E, 0x00700000u, F, 0x00000007u, c[15]);
    PAIR(a0, F, 0x00000038u, F, 0x000001C0u, c[16]);
}

// Kernel 2: out[o] += scales[o] * sum_k x[k]*q[k,o] over this block's K-chunk.
// Each thread handles 2 consecutive output columns (int2 loads), with software-
// pipelined weight loads and coefficient hoisting into registers per group.
__global__ __launch_bounds__(TPB)
void k_main(const float* __restrict__ x,
            const int*   __restrict__ qw,
            const float* __restrict__ scales,
            float* __restrict__ out,
            int OUTF)
{
    __shared__ __align__(16) float cs[NGPB * 36];

    const int tid = threadIdx.x;
    const int gbase = blockIdx.y * NGPB;
    const int colbase = blockIdx.x * (TPB * CPT) + tid * CPT;

    // Build prescaled coefficient table for this K-chunk.
    for (int idx = tid; idx < NGPB * 34; idx += TPB) {
        int g = idx / 34, k = idx - g * 34;
        cs[g * 36 + k] = x[(gbase + g) * 32 + KOFF[k]] * KSCALE[k];
    }
    __syncthreads();

    const ull NEG64 = 0xCB000000CB000000ull;  // packed {-2^23, -2^23}
    const int rowstride2 = OUTF / 2;          // int2 stride between qweight rows

    ull a00 = 0ull, a01 = 0ull, a10 = 0ull, a11 = 0ull;

    const int2* row = (const int2*)(qw + (long)gbase * 3 * OUTF + colbase);

    // prefetch group 0 weights
    int2 w0 = row[0];
    int2 w1 = row[rowstride2];
    int2 w2 = row[2 * rowstride2];

    #pragma unroll
    for (int g = 0; g < NGPB; ++g) {
        int2 n0, n1, n2;
        if (g + 1 < NGPB) {
            const int2* nrow = row + 3 * rowstride2;
            n0 = nrow[0];
            n1 = nrow[rowstride2];
            n2 = nrow[2 * rowstride2];
            row = nrow;
        }

        // hoist this group's 17 coefficient pairs into registers
        ull c[17];
        const ull* cp = (const ull*)&cs[g * 36];
        #pragma unroll
        for (int k = 0; k < 17; ++k) c[k] = cp[k];

        docol(a00, a01, (unsigned)w0.x, (unsigned)w1.x, (unsigned)w2.x, c, NEG64);
        docol(a10, a11, (unsigned)w0.y, (unsigned)w1.y, (unsigned)w2.y, c, NEG64);

        w0 = n0; w1 = n1; w2 = n2;
    }

    {
        float s0 = __uint_as_float((unsigned)a00) + __uint_as_float((unsigned)(a00 >> 32));
        float s1 = __uint_as_float((unsigned)a01) + __uint_as_float((unsigned)(a01 >> 32));
        int o = colbase;
        atomicAdd(&out[o], scales[o] * (s0 + s1));
    }
    {
        float s0 = __uint_as_float((unsigned)a10) + __uint_as_float((unsigned)(a10 >> 32));
        float s1 = __uint_as_float((unsigned)a11) + __uint_as_float((unsigned)(a11 >> 32));
        int o = colbase + 1;
        atomicAdd(&out[o], scales[o] * (s0 + s1));
    }
}

extern "C" void kernel_launch(void* const* d_in, const int* in_sizes, int n_in,
                              void* d_out, int out_size)
{
    const float* x      = (const float*)d_in[0];
    const int*   qw     = (const int*)  d_in[1];
    const float* scales = (const float*)d_in[2];
    const float* zeros  = (const float*)d_in[3];
    const float* bias   = (const float*)d_in[4];
    const float* ow     = (const float*)d_in[5];
    const int*   oidx   = (const int*)  d_in[6];
    float* out = (float*)d_out;

    const int INF  = in_sizes[0];          // 8192
    const int OUTF = in_sizes[2];          // 8192
    const int NOUT = in_sizes[6];          // 64
    const int ngroups = INF / 32;          // 256

    k_const<<<OUTF / KTPB, KTPB>>>(x, zeros, bias, ow, oidx, out, INF, NOUT);

    dim3 grid(OUTF / (TPB * CPT), ngroups / NGPB);  // (32, 64) = 2048 blocks
    k_main<<<grid, TPB>>>(x, qw, scales, out, OUTF);
}

// round 4
// speedup vs baseline: 1.2578x; 1.0208x over previous
#include <cuda_runtime.h>

#define TPB  128
#define NGPB 4        // groups (of 32 inputs) per block
#define CPT  2        // output columns per thread

typedef unsigned long long ull;

// Coefficient table: 34 entries per group, in PAIR order (entries 2p, 2p+1 form f32x2 pair p).
// Field value as float (after magic-subtract) == q * 2^s exactly; coeff = x[off] * KSCALE
// so fma gives q*x exactly.
__device__ const int KOFF[34] = {
    0,1, 2,3, 4,5, 6,7, 8,9, 10,10, 11,12, 13,14, 15,16, 17,18,
    19,20, 21,21, 22,23, 24,25, 26,27, 28,29, 30,31
};
__device__ const float KSCALE[34] = {
    0x1p0f, 0x1p-3f, 0x1p-6f, 0x1p-9f, 0x1p-12f, 0x1p-15f, 0x1p-18f,   // A fields j=0..6
    0x1p0f, 0x1p-3f, 0x1p-6f,                                          // B fields j=7..9 (r0>>21)
    0x1p-9f,                                                           // w10 lo (B bits 9-10)
    4.0f,                                                              // w10 hi (r1 bit 0)
    0x1p-1f, 0x1p-4f, 0x1p-7f, 0x1p-10f, 0x1p-13f, 0x1p-16f, 0x1p-19f, // C fields j=0..6
    0x1p0f, 0x1p-3f, 0x1p-6f,                                          // D fields j=7..9 (r1>>22)
    0x1p-9f,                                                           // w21 lo (D bit 9)
    2.0f,                                                              // w21 hi (r2 bits 0-1)
    0x1p-2f, 0x1p-5f, 0x1p-8f, 0x1p-11f, 0x1p-14f, 0x1p-17f, 0x1p-20f, // E fields j=0..6
    0x1p0f, 0x1p-3f, 0x1p-6f                                           // F fields j=7..9 (r2>>23)
};

// One packed step: two masked fields -> float pair via magic constant, subtract 2^23
// (exact), fma into packed accumulator.
#define PAIR(acc, va, ma, vb, mb, cp) do {                                        \
    ull _t;                                                                       \
    asm("mov.b64 %0, {%1,%2};" : "=l"(_t)                                         \
        : "r"(((va) & (ma)) | 0x4B000000u), "r"(((vb) & (mb)) | 0x4B000000u));    \
    asm("add.rn.f32x2 %0, %0, %1;" : "+l"(_t) : "l"(NEG64));                      \
    asm("fma.rn.f32x2 %0, %1, %2, %0;" : "+l"(acc) : "l"(_t), "l"(cp));           \
} while (0)

// Process one 32-input group for TWO columns, sharing each coefficient register.
__device__ __forceinline__ void docol2(
    ull& a00, ull& a01, ull& a10, ull& a11,
    unsigned A0, unsigned C0, unsigned E0,
    unsigned A1, unsigned C1, unsigned E1,
    const ull* __restrict__ cp, ull NEG64)
{
    unsigned B0 = A0 >> 21, D0 = C0 >> 22, F0 = E0 >> 23;
    unsigned B1 = A1 >> 21, D1 = C1 >> 22, F1 = E1 >> 23;
    ull c;
    c = cp[0];  PAIR(a00, A0, 0x00000007u, A0, 0x00000038u, c);
                PAIR(a10, A1, 0x00000007u, A1, 0x00000038u, c);
    c = cp[1];  PAIR(a01, A0, 0x000001C0u, A0, 0x00000E00u, c);
                PAIR(a11, A1, 0x000001C0u, A1, 0x00000E00u, c);
    c = cp[2];  PAIR(a00, A0, 0x00007000u, A0, 0x00038000u, c);
                PAIR(a10, A1, 0x00007000u, A1, 0x00038000u, c);
    c = cp[3];  PAIR(a01, A0, 0x001C0000u, B0, 0x00000007u, c);
                PAIR(a11, A1, 0x001C0000u, B1, 0x00000007u, c);
    c = cp[4];  PAIR(a00, B0, 0x00000038u, B0, 0x000001C0u, c);
                PAIR(a10, B1, 0x00000038u, B1, 0x000001C0u, c);
    c = cp[5];  PAIR(a01, B0, 0x00000600u, C0, 0x00000001u, c);
                PAIR(a11, B1, 0x00000600u, C1, 0x00000001u, c);
    c = cp[6];  PAIR(a00, C0, 0x0000000Eu, C0, 0x00000070u, c);
                PAIR(a10, C1, 0x0000000Eu, C1, 0x00000070u, c);
    c = cp[7];  PAIR(a01, C0, 0x00000380u, C0, 0x00001C00u, c);
                PAIR(a11, C1, 0x00000380u, C1, 0x00001C00u, c);
    c = cp[8];  PAIR(a00, C0, 0x0000E000u, C0, 0x00070000u, c);
                PAIR(a10, C1, 0x0000E000u, C1, 0x00070000u, c);
    c = cp[9];  PAIR(a01, C0, 0x00380000u, D0, 0x00000007u, c);
                PAIR(a11, C1, 0x00380000u, D1, 0x00000007u, c);
    c = cp[10]; PAIR(a00, D0, 0x00000038u, D0, 0x000001C0u, c);
                PAIR(a10, D1, 0x00000038u, D1, 0x000001C0u, c);
    c = cp[11]; PAIR(a01, D0, 0x00000200u, E0, 0x00000003u, c);
                PAIR(a11, D1, 0x00000200u, E1, 0x00000003u, c);
    c = cp[12]; PAIR(a00, E0, 0x0000001Cu, E0, 0x000000E0u, c);
                PAIR(a10, E1, 0x0000001Cu, E1, 0x000000E0u, c);
    c = cp[13]; PAIR(a01, E0, 0x00000700u, E0, 0x00003800u, c);
                PAIR(a11, E1, 0x00000700u, E1, 0x00003800u, c);
    c = cp[14]; PAIR(a00, E0, 0x0001C000u, E0, 0x000E0000u, c);
                PAIR(a10, E1, 0x0001C000u, E1, 0x000E0000u, c);
    c = cp[15]; PAIR(a01, E0, 0x00700000u, F0, 0x00000007u, c);
                PAIR(a11, E1, 0x00700000u, F1, 0x00000007u, c);
    c = cp[16]; PAIR(a00, F0, 0x00000038u, F0, 0x000001C0u, c);
                PAIR(a10, F1, 0x00000038u, F1, 0x000001C0u, c);
}

// Fused kernel: every block accumulates its K-chunk of the quantized GEMV into
// out via atomicAdd. blockIdx.y==0 blocks additionally fold in
// bias - zeros*sum(x) + oweight @ x[outlieridx] for their columns.
// out must be zeroed before launch (cudaMemsetAsync).
__global__ __launch_bounds__(TPB, 8)
void k_fused(const float* __restrict__ x,
             const int*   __restrict__ qw,
             const float* __restrict__ scales,
             const float* __restrict__ zeros,
             const float* __restrict__ bias,
             const float* __restrict__ oweight,
             const int*   __restrict__ outlieridx,
             float* __restrict__ out,
             int OUTF, int INF, int NOUT)
{
    __shared__ __align__(16) float cs[NGPB * 36];
    __shared__ float wred[TPB / 32];
    __shared__ float xo[64];

    const int tid = threadIdx.x;
    const int gbase = blockIdx.y * NGPB;
    const int colbase = blockIdx.x * (TPB * CPT) + tid * CPT;
    const bool doconst = (blockIdx.y == 0);

    if (doconst) {
        // block-wide sum(x) + gather outlier x values
        float s = 0.f;
        const float4* x4 = (const float4*)x;
        for (int i = tid; i < INF / 4; i += TPB) {
            float4 v = x4[i];
            s += (v.x + v.y) + (v.z + v.w);
        }
        #pragma unroll
        for (int d = 16; d > 0; d >>= 1) s += __shfl_xor_sync(0xFFFFFFFFu, s, d);
        if ((tid & 31) == 0) wred[tid >> 5] = s;
        if (tid < NOUT) xo[tid] = x[outlieridx[tid]];
    }

    // Build prescaled coefficient table for this K-chunk.
    for (int idx = tid; idx < NGPB * 34; idx += TPB) {
        int g = idx / 34, k = idx - g * 34;
        cs[g * 36 + k] = x[(gbase + g) * 32 + KOFF[k]] * KSCALE[k];
    }
    __syncthreads();

    const ull NEG64 = 0xCB000000CB000000ull;  // packed {-2^23, -2^23}
    const int rowstride2 = OUTF / 2;          // int2 stride between qweight rows

    ull a00 = 0ull, a01 = 0ull, a10 = 0ull, a11 = 0ull;

    const int2* row = (const int2*)(qw + (long)gbase * 3 * OUTF + colbase);

    // prefetch group 0 weights
    int2 w0 = row[0];
    int2 w1 = row[rowstride2];
    int2 w2 = row[2 * rowstride2];

    #pragma unroll
    for (int g = 0; g < NGPB; ++g) {
        int2 n0, n1, n2;
        if (g + 1 < NGPB) {
            const int2* nrow = row + 3 * rowstride2;
            n0 = nrow[0];
            n1 = nrow[rowstride2];
            n2 = nrow[2 * rowstride2];
            row = nrow;
        }

        const ull* cp = (const ull*)&cs[g * 36];
        docol2(a00, a01, a10, a11,
               (unsigned)w0.x, (unsigned)w1.x, (unsigned)w2.x,
               (unsigned)w0.y, (unsigned)w1.y, (unsigned)w2.y,
               cp, NEG64);

        w0 = n0; w1 = n1; w2 = n2;
    }

    const int o0 = colbase, o1 = colbase + 1;

    float base0 = 0.f, base1 = 0.f;
    if (doconst) {
        const float sumx = wred[0] + wred[1] + wred[2] + wred[3];
        base0 = bias[o0] - zeros[o0] * sumx;
        base1 = bias[o1] - zeros[o1] * sumx;
        const float4* ow0 = (const float4*)(oweight + (size_t)o0 * NOUT);
        const float4* ow1 = (const float4*)(oweight + (size_t)o1 * NOUT);
        #pragma unroll 8
        for (int j = 0; j < NOUT / 4; ++j) {
            float4 u = ow0[j];
            float4 v = ow1[j];
            float q0 = xo[4 * j + 0], q1 = xo[4 * j + 1];
            float q2 = xo[4 * j + 2], q3 = xo[4 * j + 3];
            base0 = fmaf(u.x, q0, base0);
            base1 = fmaf(v.x, q0, base1);
            base0 = fmaf(u.y, q1, base0);
            base1 = fmaf(v.y, q1, base1);
            base0 = fmaf(u.z, q2, base0);
            base1 = fmaf(v.z, q2, base1);
            base0 = fmaf(u.w, q3, base0);
            base1 = fmaf(v.w, q3, base1);
        }
    }

    {
        float s0 = __uint_as_float((unsigned)a00) + __uint_as_float((unsigned)(a00 >> 32));
        float s1 = __uint_as_float((unsigned)a01) + __uint_as_float((unsigned)(a01 >> 32));
        atomicAdd(&out[o0], fmaf(scales[o0], s0 + s1, base0));
    }
    {
        float s0 = __uint_as_float((unsigned)a10) + __uint_as_float((unsigned)(a10 >> 32));
        float s1 = __uint_as_float((unsigned)a11) + __uint_as_float((unsigned)(a11 >> 32));
        atomicAdd(&out[o1], fmaf(scales[o1], s0 + s1, base1));
    }
}

extern "C" void kernel_launch(void* const* d_in, const int* in_sizes, int n_in,
                              void* d_out, int out_size)
{
    const float* x      = (const float*)d_in[0];
    const int*   qw     = (const int*)  d_in[1];
    const float* scales = (const float*)d_in[2];
    const float* zeros  = (const float*)d_in[3];
    const float* bias   = (const float*)d_in[4];
    const float* ow     = (const float*)d_in[5];
    const int*   oidx   = (const int*)  d_in[6];
    float* out = (float*)d_out;

    const int INF  = in_sizes[0];          // 8192
    const int OUTF = in_sizes[2];          // 8192
    const int NOUT = in_sizes[6];          // 64
    const int ngroups = INF / 32;          // 256

    cudaMemsetAsync(out, 0, (size_t)out_size * sizeof(float));

    dim3 grid(OUTF / (TPB * CPT), ngroups / NGPB);  // (32, 64) = 2048 blocks
    k_fused<<<grid, TPB>>>(x, qw, scales, zeros, bias, ow, oidx, out,
                           OUTF, INF, NOUT);
}

// round 5
// speedup vs baseline: 1.3795x; 1.0968x over previous
#include <cuda_runtime.h>

#define TPB  128
#define NGPB 4        // groups (of 32 inputs) per block
#define CPT  2        // output columns per thread

typedef unsigned long long ull;

// Coefficient table: 34 entries per group, in PAIR order (entries 2p, 2p+1 form f32x2 pair p).
// Field value as float (after magic-subtract) == q * 2^s exactly; coeff = x[off] * KSCALE
// so fma gives q*x exactly.
__device__ const int KOFF[34] = {
    0,1, 2,3, 4,5, 6,7, 8,9, 10,10, 11,12, 13,14, 15,16, 17,18,
    19,20, 21,21, 22,23, 24,25, 26,27, 28,29, 30,31
};
__device__ const float KSCALE[34] = {
    0x1p0f, 0x1p-3f, 0x1p-6f, 0x1p-9f, 0x1p-12f, 0x1p-15f, 0x1p-18f,   // A fields j=0..6
    0x1p0f, 0x1p-3f, 0x1p-6f,                                          // B fields j=7..9 (r0>>21)
    0x1p-9f,                                                           // w10 lo (B bits 9-10)
    4.0f,                                                              // w10 hi (r1 bit 0)
    0x1p-1f, 0x1p-4f, 0x1p-7f, 0x1p-10f, 0x1p-13f, 0x1p-16f, 0x1p-19f, // C fields j=0..6
    0x1p0f, 0x1p-3f, 0x1p-6f,                                          // D fields j=7..9 (r1>>22)
    0x1p-9f,                                                           // w21 lo (D bit 9)
    2.0f,                                                              // w21 hi (r2 bits 0-1)
    0x1p-2f, 0x1p-5f, 0x1p-8f, 0x1p-11f, 0x1p-14f, 0x1p-17f, 0x1p-20f, // E fields j=0..6
    0x1p0f, 0x1p-3f, 0x1p-6f                                           // F fields j=7..9 (r2>>23)
};

// One packed step: two masked fields -> float pair via magic constant, subtract 2^23
// (exact), fma into packed accumulator.
#define PAIR(acc, va, ma, vb, mb, cp) do {                                        \
    ull _t;                                                                       \
    asm("mov.b64 %0, {%1,%2};" : "=l"(_t)                                         \
        : "r"(((va) & (ma)) | 0x4B000000u), "r"(((vb) & (mb)) | 0x4B000000u));    \
    asm("add.rn.f32x2 %0, %0, %1;" : "+l"(_t) : "l"(NEG64));                      \
    asm("fma.rn.f32x2 %0, %1, %2, %0;" : "+l"(acc) : "l"(_t), "l"(cp));           \
} while (0)

// Process one 32-input group for TWO columns. Coefficients read as 9 x LDS.128
// (ulonglong2); each vector's .x/.y feed consecutive pairs for both columns.
__device__ __forceinline__ void docol2(
    ull& a00, ull& a01, ull& a10, ull& a11,
    unsigned A0, unsigned C0, unsigned E0,
    unsigned A1, unsigned C1, unsigned E1,
    const ulonglong2* __restrict__ cp, ull NEG64)
{
    unsigned B0 = A0 >> 21, D0 = C0 >> 22, F0 = E0 >> 23;
    unsigned B1 = A1 >> 21, D1 = C1 >> 22, F1 = E1 >> 23;
    ulonglong2 v;
    v = cp[0];
    PAIR(a00, A0, 0x00000007u, A0, 0x00000038u, v.x);
    PAIR(a10, A1, 0x00000007u, A1, 0x00000038u, v.x);
    PAIR(a01, A0, 0x000001C0u, A0, 0x00000E00u, v.y);
    PAIR(a11, A1, 0x000001C0u, A1, 0x00000E00u, v.y);
    v = cp[1];
    PAIR(a00, A0, 0x00007000u, A0, 0x00038000u, v.x);
    PAIR(a10, A1, 0x00007000u, A1, 0x00038000u, v.x);
    PAIR(a01, A0, 0x001C0000u, B0, 0x00000007u, v.y);
    PAIR(a11, A1, 0x001C0000u, B1, 0x00000007u, v.y);
    v = cp[2];
    PAIR(a00, B0, 0x00000038u, B0, 0x000001C0u, v.x);
    PAIR(a10, B1, 0x00000038u, B1, 0x000001C0u, v.x);
    PAIR(a01, B0, 0x00000600u, C0, 0x00000001u, v.y);
    PAIR(a11, B1, 0x00000600u, C1, 0x00000001u, v.y);
    v = cp[3];
    PAIR(a00, C0, 0x0000000Eu, C0, 0x00000070u, v.x);
    PAIR(a10, C1, 0x0000000Eu, C1, 0x00000070u, v.x);
    PAIR(a01, C0, 0x00000380u, C0, 0x00001C00u, v.y);
    PAIR(a11, C1, 0x00000380u, C1, 0x00001C00u, v.y);
    v = cp[4];
    PAIR(a00, C0, 0x0000E000u, C0, 0x00070000u, v.x);
    PAIR(a10, C1, 0x0000E000u, C1, 0x00070000u, v.x);
    PAIR(a01, C0, 0x00380000u, D0, 0x00000007u, v.y);
    PAIR(a11, C1, 0x00380000u, D1, 0x00000007u, v.y);
    v = cp[5];
    PAIR(a00, D0, 0x00000038u, D0, 0x000001C0u, v.x);
    PAIR(a10, D1, 0x00000038u, D1, 0x000001C0u, v.x);
    PAIR(a01, D0, 0x00000200u, E0, 0x00000003u, v.y);
    PAIR(a11, D1, 0x00000200u, E1, 0x00000003u, v.y);
    v = cp[6];
    PAIR(a00, E0, 0x0000001Cu, E0, 0x000000E0u, v.x);
    PAIR(a10, E1, 0x0000001Cu, E1, 0x000000E0u, v.x);
    PAIR(a01, E0, 0x00000700u, E0, 0x00003800u, v.y);
    PAIR(a11, E1, 0x00000700u, E1, 0x00003800u, v.y);
    v = cp[7];
    PAIR(a00, E0, 0x0001C000u, E0, 0x000E0000u, v.x);
    PAIR(a10, E1, 0x0001C000u, E1, 0x000E0000u, v.x);
    PAIR(a01, E0, 0x00700000u, F0, 0x00000007u, v.y);
    PAIR(a11, E1, 0x00700000u, F1, 0x00000007u, v.y);
    v = cp[8];
    PAIR(a00, F0, 0x00000038u, F0, 0x000001C0u, v.x);
    PAIR(a10, F1, 0x00000038u, F1, 0x000001C0u, v.x);
}

// Fused kernel: every block accumulates its K-chunk of the quantized GEMV into
// out via atomicAdd. blockIdx.y==0 blocks additionally fold in
// bias - zeros*sum(x) + oweight @ x[outlieridx] for their columns.
// out must be zeroed before launch (cudaMemsetAsync).
__global__ __launch_bounds__(TPB, 16)
void k_fused(const float* __restrict__ x,
             const int*   __restrict__ qw,
             const float* __restrict__ scales,
             const float* __restrict__ zeros,
             const float* __restrict__ bias,
             const float* __restrict__ oweight,
             const int*   __restrict__ outlieridx,
             float* __restrict__ out,
             int OUTF, int INF, int NOUT)
{
    __shared__ __align__(16) float cs[NGPB * 36];
    __shared__ float wred[TPB / 32];
    __shared__ float xo[64];

    const int tid = threadIdx.x;
    const int gbase = blockIdx.y * NGPB;
    const int colbase = blockIdx.x * (TPB * CPT) + tid * CPT;
    const bool doconst = (blockIdx.y == 0);

    if (doconst) {
        // block-wide sum(x) + gather outlier x values
        float s = 0.f;
        const float4* x4 = (const float4*)x;
        for (int i = tid; i < INF / 4; i += TPB) {
            float4 v = x4[i];
            s += (v.x + v.y) + (v.z + v.w);
        }
        #pragma unroll
        for (int d = 16; d > 0; d >>= 1) s += __shfl_xor_sync(0xFFFFFFFFu, s, d);
        if ((tid & 31) == 0) wred[tid >> 5] = s;
        if (tid < NOUT) xo[tid] = x[outlieridx[tid]];
    }

    // Build prescaled coefficient table for this K-chunk (pad entries zeroed).
    for (int idx = tid; idx < NGPB * 36; idx += TPB) {
        int g = idx / 36, k = idx - g * 36;
        float v = 0.f;
        if (k < 34) v = x[(gbase + g) * 32 + KOFF[k]] * KSCALE[k];
        cs[idx] = v;
    }
    __syncthreads();

    const ull NEG64 = 0xCB000000CB000000ull;  // packed {-2^23, -2^23}
    const int rowstride2 = OUTF / 2;          // int2 stride between qweight rows

    ull a00 = 0ull, a01 = 0ull, a10 = 0ull, a11 = 0ull;

    const int2* row = (const int2*)(qw + (long)gbase * 3 * OUTF + colbase);

    // prefetch group 0 weights
    int2 w0 = row[0];
    int2 w1 = row[rowstride2];
    int2 w2 = row[2 * rowstride2];

    #pragma unroll
    for (int g = 0; g < NGPB; ++g) {
        int2 n0, n1, n2;
        if (g + 1 < NGPB) {
            const int2* nrow = row + 3 * rowstride2;
            n0 = nrow[0];
            n1 = nrow[rowstride2];
            n2 = nrow[2 * rowstride2];
            row = nrow;
        }

        const ulonglong2* cp = (const ulonglong2*)&cs[g * 36];
        docol2(a00, a01, a10, a11,
               (unsigned)w0.x, (unsigned)w1.x, (unsigned)w2.x,
               (unsigned)w0.y, (unsigned)w1.y, (unsigned)w2.y,
               cp, NEG64);

        w0 = n0; w1 = n1; w2 = n2;
    }

    const int o0 = colbase, o1 = colbase + 1;

    float base0 = 0.f, base1 = 0.f;
    if (doconst) {
        const float sumx = wred[0] + wred[1] + wred[2] + wred[3];
        base0 = bias[o0] - zeros[o0] * sumx;
        base1 = bias[o1] - zeros[o1] * sumx;
        const float4* ow0 = (const float4*)(oweight + (size_t)o0 * NOUT);
        const float4* ow1 = (const float4*)(oweight + (size_t)o1 * NOUT);
        #pragma unroll 8
        for (int j = 0; j < NOUT / 4; ++j) {
            float4 u = ow0[j];
            float4 v = ow1[j];
            float q0 = xo[4 * j + 0], q1 = xo[4 * j + 1];
            float q2 = xo[4 * j + 2], q3 = xo[4 * j + 3];
            base0 = fmaf(u.x, q0, base0);
            base1 = fmaf(v.x, q0, base1);
            base0 = fmaf(u.y, q1, base0);
            base1 = fmaf(v.y, q1, base1);
            base0 = fmaf(u.z, q2, base0);
            base1 = fmaf(v.z, q2, base1);
            base0 = fmaf(u.w, q3, base0);
            base1 = fmaf(v.w, q3, base1);
        }
    }

    {
        float s0 = __uint_as_float((unsigned)a00) + __uint_as_float((unsigned)(a00 >> 32));
        float s1 = __uint_as_float((unsigned)a01) + __uint_as_float((unsigned)(a01 >> 32));
        atomicAdd(&out[o0], fmaf(scales[o0], s0 + s1, base0));
    }
    {
        float s0 = __uint_as_float((unsigned)a10) + __uint_as_float((unsigned)(a10 >> 32));
        float s1 = __uint_as_float((unsigned)a11) + __uint_as_float((unsigned)(a11 >> 32));
        atomicAdd(&out[o1], fmaf(scales[o1], s0 + s1, base1));
    }
}

extern "C" void kernel_launch(void* const* d_in, const int* in_sizes, int n_in,
                              void* d_out, int out_size)
{
    const float* x      = (const float*)d_in[0];
    const int*   qw     = (const int*)  d_in[1];
    const float* scales = (const float*)d_in[2];
    const float* zeros  = (const float*)d_in[3];
    const float* bias   = (const float*)d_in[4];
    const float* ow     = (const float*)d_in[5];
    const int*   oidx   = (const int*)  d_in[6];
    float* out = (float*)d_out;

    const int INF  = in_sizes[0];          // 8192
    const int OUTF = in_sizes[2];          // 8192
    const int NOUT = in_sizes[6];          // 64
    const int ngroups = INF / 32;          // 256

    cudaMemsetAsync(out, 0, (size_t)out_size * sizeof(float));

    dim3 grid(OUTF / (TPB * CPT), ngroups / NGPB);  // (32, 64) = 2048 blocks
    k_fused<<<grid, TPB>>>(x, qw, scales, zeros, bias, ow, oidx, out,
                           OUTF, INF, NOUT);
}